// round 10
// baseline (speedup 1.0000x reference)
#include <cuda_runtime.h>
#include <math.h>

// ---------------------------------------------------------------------------
// LocalPseudoFeatLoss: B=2, C=19, H=W=128, CH=64, K=7, TOPK=8
// 8 lanes/pixel; lane i holds channels {4i..4i+3, 32+4i..32+4i+3} so each
// warp-load covers whole 128B lines (fully coalesced).
// ---------------------------------------------------------------------------

namespace {
constexpr int NC   = 19;
constexpr int NCP  = 20;     // padded classes
constexpr int HH   = 128;
constexpr int WW   = 128;
constexpr int HWp  = HH * WW;
constexpr int FC   = 64;
constexpr int KK   = 7;
constexpr int K2   = KK * KK;
constexpr int NTOP = 9;
constexpr int NBOT = 8;
constexpr int NPIX = 2 * HWp;
constexpr float EPSV = 1e-8f;
constexpr int FB = FC * 4;    // feature row bytes (256)
constexpr int PB = NCP * 4;   // prob row bytes
constexpr int NT = NPIX / 32; // transpose blocks per tensor (1024)
constexpr int SRC_BLOCKS = 1024;
constexpr int TRG_BLOCKS = 1024;
constexpr int MAIN_BLOCKS = SRC_BLOCKS + TRG_BLOCKS;
}

__device__ float  g_xs[NPIX * FC];     // normalized x_src, pixel-major
__device__ float  g_xe[NPIX * FC];     // normalized x_ema, pixel-major
__device__ float  g_pp[NPIX * NCP];    // softmax(logits), pixel-major, padded
__device__ double g_acc[8];
__device__ int    g_done;
// 0 sum_src_pos  1 cnt_src_pos  2 sum_src_neg  3 n_valid_src
// 4 sum_sim_pos  5 sum_sim_neg  6 cnt_trg

__device__ __forceinline__ float dot4(float4 a, float4 b) {
    float d = a.x * b.x;
    d = fmaf(a.y, b.y, d);
    d = fmaf(a.z, b.z, d);
    d = fmaf(a.w, b.w, d);
    return d;
}

__device__ __forceinline__ unsigned ord_of_f(float f) {
    unsigned b = __float_as_uint(f);
    return b ^ (((unsigned)((int)b >> 31)) | 0x80000000u);
}
__device__ __forceinline__ float f_of_ord(unsigned u) {
    unsigned b = (u & 0x80000000u) ? (u ^ 0x80000000u) : ~u;
    return __uint_as_float(b);
}

// Reduce 8 values across 8 lanes (3 exchange stages).
// On return, lane n of the 8-lane segment holds the total of value n (in v[0]).
__device__ __forceinline__ void tree8x8(float v[8], unsigned mask, int lane) {
    {   bool hi = (lane & 4) != 0;
        #pragma unroll
        for (int j = 0; j < 4; j++) {
            float mine = hi ? v[j] : v[j + 4];
            float kept = hi ? v[j + 4] : v[j];
            v[j] = kept + __shfl_xor_sync(mask, mine, 4);
        } }
    {   bool hi = (lane & 2) != 0;
        #pragma unroll
        for (int j = 0; j < 2; j++) {
            float mine = hi ? v[j] : v[j + 2];
            float kept = hi ? v[j + 2] : v[j];
            v[j] = kept + __shfl_xor_sync(mask, mine, 2);
        } }
    {   bool hi = (lane & 1) != 0;
        float mine = hi ? v[0] : v[1];
        float kept = hi ? v[1] : v[0];
        v[0] = kept + __shfl_xor_sync(mask, mine, 1);
    }
}

// ---- fused prep: blocks [0,NT) transpose xs, [NT,2NT) xe, rest softmax ----
__device__ __forceinline__ void transpose_block(const float* __restrict__ src,
                                                float* __restrict__ dst,
                                                int blk, int t) {
    __shared__ float sm[FC][33];
    int pix0 = blk * 32;
    int b   = pix0 / HWp;
    int hw0 = pix0 - b * HWp;

    int px = t & 31, cb = (t >> 5) * 8;
    const float* sp = src + (size_t)b * FC * HWp + hw0 + px;
    #pragma unroll
    for (int j = 0; j < 8; j++)
        sm[cb + j][px] = sp[(size_t)(cb + j) * HWp];
    __syncthreads();

    int px2 = t >> 3, part = t & 7;
    float v[8];
    float ss = 0.f;
    #pragma unroll
    for (int j = 0; j < 8; j++) {
        v[j] = sm[part * 8 + j][px2];
        ss = fmaf(v[j], v[j], ss);
    }
    #pragma unroll
    for (int o = 4; o; o >>= 1) ss += __shfl_xor_sync(0xffffffffu, ss, o);
    float rn = 1.f / fmaxf(sqrtf(ss), EPSV);
    float4* d = reinterpret_cast<float4*>(dst + (size_t)(pix0 + px2) * FC + part * 8);
    d[0] = make_float4(v[0] * rn, v[1] * rn, v[2] * rn, v[3] * rn);
    d[1] = make_float4(v[4] * rn, v[5] * rn, v[6] * rn, v[7] * rn);
}

__global__ void __launch_bounds__(256)
k_prep(const float* __restrict__ xs, const float* __restrict__ xe,
       const float* __restrict__ logits) {
    int bx = blockIdx.x;
    int t = threadIdx.x;
    if (bx < NT) {
        transpose_block(xs, g_xs, bx, t);
    } else if (bx < 2 * NT) {
        transpose_block(xe, g_xe, bx - NT, t);
    } else {
        int sb = bx - 2 * NT;
        if (sb == 0 && t < 8) g_acc[t] = 0.0;
        if (sb == 0 && t == 8) g_done = 0;
        int pix = sb * 256 + t;
        if (pix >= NPIX) return;
        int b  = pix / HWp;
        int hw = pix - b * HWp;
        const float* lb = logits + (size_t)b * NC * HWp + hw;
        float l[NC];
        float mx = -3.4e38f;
        #pragma unroll
        for (int c = 0; c < NC; c++) {
            l[c] = lb[(size_t)c * HWp];
            mx = fmaxf(mx, l[c]);
        }
        float s = 0.f;
        #pragma unroll
        for (int c = 0; c < NC; c++) { l[c] = expf(l[c] - mx); s += l[c]; }
        float inv = 1.f / s;
        #pragma unroll
        for (int c = 0; c < NC; c++) g_pp[(size_t)pix * NCP + c] = l[c] * inv;
        g_pp[(size_t)pix * NCP + NC] = 0.f;
    }
}

// ---- src path: pair-symmetric, 24 forward neighbors + analytic center ----
__device__ __forceinline__ void src_path(const int* __restrict__ gt, int bx) {
    int b  = bx >> 9;
    int tt = bx & 511;                // 16x32 tiles of 8x4
    int h0 = (tt >> 5) << 3;
    int w0 = (tt & 31) << 2;
    int g    = threadIdx.x >> 3;      // 0..31 pixel in tile
    int lane = threadIdx.x & 7;
    unsigned gmask = 0xFFu << (threadIdx.x & 24);
    int h = h0 + (g >> 2), w = w0 + (g & 3);
    int pix = b * HWp + h * WW + w;

    bool interior = (h0 >= 8) && (h0 <= 112) && (w0 >= 4) && (w0 <= 120);

    int gc = gt[pix];
    float wp = (gc != 255) ? 1.f : 0.f;

    float sp = 0.f, sn = 0.f, cp = 0.f, nv = 0.f;

    // coalesced slice: lane covers bytes [lane*16,+16) and [128+lane*16,+16)
    const char* Pl = (const char*)g_xs + (size_t)pix * FB + lane * 16;
    float4 f0 = *(const float4*)Pl;
    float4 f1 = *(const float4*)(Pl + 128);
    const int* Pg = gt + pix;

    if (interior) {
        #pragma unroll
        for (int c = 0; c < 3; c++) {
            #pragma unroll
            for (int n = 0; n < 8; n++) {
                int k  = 25 + c * 8 + n;         // compile-time
                int dy = k / KK - 3;
                int dx = k - (k / KK) * KK - 3;
                int off = dy * WW + dx;
                float4 n0 = *(const float4*)(Pl + (ptrdiff_t)off * FB);
                float4 n1 = *(const float4*)(Pl + (ptrdiff_t)off * FB + 128);
                float s = dot4(f0, n0) + dot4(f1, n1);
                int gq = Pg[off];
                float wgt = wp + ((gq != 255) ? 1.f : 0.f);
                if (gq == gc) sp = fmaf(wgt, s, sp);
                else          sn = fmaf(wgt, s, sn);
            }
        }
    } else {
        #pragma unroll 1
        for (int k = 25; k < K2; k++) {
            int dy = k / KK - 3;
            int dx = k - (k / KK) * KK - 3;
            int hn = h + dy, wn = w + dx;
            if ((unsigned)hn < (unsigned)HH && (unsigned)wn < (unsigned)WW) {
                int off = dy * WW + dx;
                float4 n0 = *(const float4*)(Pl + (ptrdiff_t)off * FB);
                float4 n1 = *(const float4*)(Pl + (ptrdiff_t)off * FB + 128);
                float s = dot4(f0, n0) + dot4(f1, n1);
                int gq = Pg[off];
                float wgt = wp + ((gq != 255) ? 1.f : 0.f);
                if (gq == gc) sp = fmaf(wgt, s, sp);
                else          sn = fmaf(wgt, s, sn);
            }
        }
    }
    if (lane == 0) {
        sp += wp;        // center pair (k=24): sim = 1, pos
        nv  = wp;
    }

    if (gc != 255) {
        if (interior) {
            #pragma unroll 1
            for (int k = lane; k < K2; k += 8) {
                int dy = ((k * 9363) >> 16) - 3;       // k/7 - 3
                int dx = k - (dy + 3) * KK - 3;
                if (Pg[dy * WW + dx] == gc) cp += 1.f;
            }
        } else {
            #pragma unroll 1
            for (int k = lane; k < K2; k += 8) {
                int dy = ((k * 9363) >> 16) - 3;
                int dx = k - (dy + 3) * KK - 3;
                int hn = h + dy, wn = w + dx;
                int gn = 0;
                if ((unsigned)hn < (unsigned)HH && (unsigned)wn < (unsigned)WW)
                    gn = Pg[dy * WW + dx];
                if (gn == gc) cp += 1.f;
            }
        }
    }

    #pragma unroll
    for (int o = 4; o; o >>= 1) {
        sp += __shfl_xor_sync(gmask, sp, o);
        sn += __shfl_xor_sync(gmask, sn, o);
        cp += __shfl_xor_sync(gmask, cp, o);
        nv += __shfl_xor_sync(gmask, nv, o);
    }
    __shared__ float sa[4];
    if (threadIdx.x < 4) sa[threadIdx.x] = 0.f;
    __syncthreads();
    if (lane == 0) {
        atomicAdd(&sa[0], sp);
        atomicAdd(&sa[1], cp);
        atomicAdd(&sa[2], sn);
        atomicAdd(&sa[3], nv);
    }
    __syncthreads();
    if (threadIdx.x == 0) {
        atomicAdd(&g_acc[0], (double)sa[0]);
        atomicAdd(&g_acc[1], (double)sa[1]);
        atomicAdd(&g_acc[2], (double)sa[2]);
        atomicAdd(&g_acc[3], (double)sa[3]);
    }
}

// ---- trg path: sims -> packed-key top-k -> selected cross-probs ----
__device__ __forceinline__ void trg_path(const float* __restrict__ mix, int bx) {
    __shared__ float sm_s[K2][36];   // pad 36: conflict-free tree stores/reads
    __shared__ unsigned long long sel[32][18];
    __shared__ float sred[3];

    int b  = bx >> 9;
    int tt = bx & 511;                // 16x32 tiles of 8x4
    int h0 = (tt >> 5) << 3;
    int w0 = (tt & 31) << 2;
    int g    = threadIdx.x >> 3;      // 0..31 pixel in tile
    int lane = threadIdx.x & 7;
    unsigned gmask = 0xFFu << (threadIdx.x & 24);
    int h = h0 + (g >> 2), w = w0 + (g & 3);
    int pix = b * HWp + h * WW + w;

    bool interior = (h0 >= 8) && (h0 <= 112) && (w0 >= 4) && (w0 <= 120);
    bool act = (1.f - mix[pix]) > 0.5f;

    if (act) {
        const char* Pl = (const char*)g_xe + (size_t)pix * FB + lane * 16;
        float4 f0 = *(const float4*)Pl;
        float4 f1 = *(const float4*)(Pl + 128);
        if (interior) {
            #pragma unroll
            for (int c = 0; c < 6; c++) {
                float sv[8];
                #pragma unroll
                for (int n = 0; n < 8; n++) {
                    int k  = c * 8 + n;
                    int dy = k / KK - 3;
                    int dx = k - (k / KK) * KK - 3;
                    int off = dy * WW + dx;
                    float4 n0 = *(const float4*)(Pl + (ptrdiff_t)off * FB);
                    float4 n1 = *(const float4*)(Pl + (ptrdiff_t)off * FB + 128);
                    sv[n] = dot4(f0, n0) + dot4(f1, n1);
                }
                tree8x8(sv, gmask, lane);
                sm_s[c * 8 + lane][g] = sv[0];
            }
            {   // straggler k = 48
                float4 n0 = *(const float4*)(Pl + (ptrdiff_t)(3 * WW + 3) * FB);
                float4 n1 = *(const float4*)(Pl + (ptrdiff_t)(3 * WW + 3) * FB + 128);
                float pd = dot4(f0, n0) + dot4(f1, n1);
                #pragma unroll
                for (int o = 4; o; o >>= 1)
                    pd += __shfl_xor_sync(gmask, pd, o);
                if (lane == 0) sm_s[48][g] = pd;
            }
        } else {
            int k = 0;
            #pragma unroll 1
            for (int ky = 0; ky < KK; ky++) {
                int hn = h + ky - 3;
                bool rv = (unsigned)hn < (unsigned)HH;
                int hc = min(max(hn, 0), HH - 1);
                #pragma unroll
                for (int kx = 0; kx < KK; kx++, k++) {
                    int wn = w + kx - 3;
                    bool ok = rv && ((unsigned)wn < (unsigned)WW);
                    int wc = min(max(wn, 0), WW - 1);
                    int pn = b * HWp + hc * WW + wc;
                    const char* Pn = (const char*)g_xe + (size_t)pn * FB + lane * 16;
                    float4 n0 = *(const float4*)Pn;
                    float4 n1 = *(const float4*)(Pn + 128);
                    float pd = dot4(f0, n0) + dot4(f1, n1);
                    #pragma unroll
                    for (int o = 4; o; o >>= 1)
                        pd += __shfl_xor_sync(gmask, pd, o);
                    if (lane == 0) sm_s[k][g] = ok ? pd : 0.f;
                }
            }
        }
    }
    if (threadIdx.x < 3) sred[threadIdx.x] = 0.f;
    __syncthreads();

    // phase 2a: selection on packed keys (64 threads, 32 top + 32 bottom)
    if (threadIdx.x < 64) {
        int t = threadIdx.x;
        int q2 = t & 31;
        int h2 = h0 + (q2 >> 2), w2 = w0 + (q2 & 3);
        int p2 = b * HWp + h2 * WW + w2;
        if ((1.f - mix[p2]) > 0.5f) {
            if (t < 32) {
                unsigned long long key[NTOP];
                #pragma unroll
                for (int i = 0; i < NTOP; i++) key[i] = 0ull;
                #pragma unroll 1
                for (int k = 0; k < K2; k++) {
                    unsigned long long kk =
                        ((unsigned long long)ord_of_f(sm_s[k][q2]) << 8)
                        | (unsigned)(63 - k);
                    if (kk > key[NTOP - 1]) {
                        #pragma unroll
                        for (int i = 0; i < NTOP; i++)
                            if (kk > key[i]) {
                                unsigned long long x = key[i]; key[i] = kk; kk = x;
                            }
                    }
                }
                #pragma unroll
                for (int i = 0; i < NTOP; i++) sel[q2][i] = key[i];
            } else {
                unsigned long long key[NBOT];
                #pragma unroll
                for (int i = 0; i < NBOT; i++) key[i] = ~0ull;
                #pragma unroll 1
                for (int k = 0; k < K2; k++) {
                    unsigned long long kk =
                        ((unsigned long long)ord_of_f(sm_s[k][q2]) << 8)
                        | (unsigned)k;
                    if (kk < key[NBOT - 1]) {
                        #pragma unroll
                        for (int i = 0; i < NBOT; i++)
                            if (kk < key[i]) {
                                unsigned long long x = key[i]; key[i] = kk; kk = x;
                            }
                    }
                }
                #pragma unroll
                for (int i = 0; i < NBOT; i++) sel[q2][NTOP + i] = key[i];
            }
        }
    }
    __syncthreads();

    // phase 2b: 17 selected prob dots per pixel (8 lanes/pixel)
    float ssp = 0.f, ssn = 0.f, cnt = 0.f;
    if (act) {
        if (lane == 0) cnt = 1.f;
        const float4* A = reinterpret_cast<const float4*>(g_pp + (size_t)pix * NCP);
        float4 A0 = A[0], A1 = A[1], A2 = A[2], A3 = A[3], A4 = A[4];
        #pragma unroll 1
        for (int tid = lane; tid < NTOP + NBOT; tid += 8) {
            unsigned long long kk = sel[g][tid];
            bool isTop = tid < NTOP;
            int k = isTop ? (63 - (int)(kk & 63u)) : (int)(kk & 63u);
            float val = f_of_ord((unsigned)(kk >> 8));
            int dy = ((k * 9363) >> 16) - 3;
            int dx = k - (dy + 3) * KK - 3;
            int hn = h + dy, wn = w + dx;
            float cpv = 1.f / 19.f;
            if ((unsigned)hn < (unsigned)HH && (unsigned)wn < (unsigned)WW) {
                const float4* Bv = reinterpret_cast<const float4*>(
                    g_pp + (size_t)(pix + dy * WW + dx) * NCP);
                float d2 = dot4(A0, Bv[0]);
                d2 += dot4(A1, Bv[1]);
                d2 += dot4(A2, Bv[2]);
                d2 += dot4(A3, Bv[3]);
                d2 += dot4(A4, Bv[4]);
                cpv = d2;
            }
            if (isTop) ssp = fmaf(val, -cpv, ssp);
            else       ssn += (1.f - val) * (-(1.f - cpv));
        }
    }
    #pragma unroll
    for (int o = 16; o; o >>= 1) {
        ssp += __shfl_xor_sync(0xffffffffu, ssp, o);
        ssn += __shfl_xor_sync(0xffffffffu, ssn, o);
        cnt += __shfl_xor_sync(0xffffffffu, cnt, o);
    }
    if ((threadIdx.x & 31) == 0) {
        atomicAdd(&sred[0], ssp);
        atomicAdd(&sred[1], ssn);
        atomicAdd(&sred[2], cnt);
    }
    __syncthreads();
    if (threadIdx.x == 0) {
        atomicAdd(&g_acc[4], (double)sred[0]);
        atomicAdd(&g_acc[5], (double)sred[1]);
        atomicAdd(&g_acc[6], (double)sred[2]);
    }
}

// ---- merged main: interleaved src/trg blocks + last-block finalize ----
__global__ void __launch_bounds__(256)
k_main(const int* __restrict__ gt, const float* __restrict__ mix,
       float* __restrict__ out) {
    int bx = blockIdx.x;
    if (bx & 1) trg_path(mix, bx >> 1);
    else        src_path(gt, bx >> 1);

    __shared__ bool isLast;
    if (threadIdx.x == 0) {
        __threadfence();
        int prev = atomicAdd(&g_done, 1);
        isLast = (prev == MAIN_BLOCKS - 1);
    }
    __syncthreads();
    if (isLast && threadIdx.x == 0) {
        double cntP = g_acc[1];
        double cntN = 49.0 * g_acc[3] - cntP;
        double src_pos = g_acc[0] / fmax(cntP, 1.0);
        double src_neg = g_acc[2] / fmax(cntN, 1.0);
        double sim_pos = g_acc[4] / fmax((double)NTOP * g_acc[6], 1.0);
        double sim_neg = g_acc[5] / fmax((double)NBOT * g_acc[6], 1.0);
        out[0] = (float)(-src_pos);
        out[1] = (float)( src_neg);
        out[2] = (float)( sim_pos);
        out[3] = (float)( sim_neg);
    }
}

extern "C" void kernel_launch(void* const* d_in, const int* in_sizes, int n_in,
                              void* d_out, int out_size) {
    (void)in_sizes; (void)n_in; (void)out_size;
    const float* logits = (const float*)d_in[0];
    const int*   gt     = (const int*)d_in[1];
    const float* xe     = (const float*)d_in[2];
    const float* xs     = (const float*)d_in[3];
    const float* mix    = (const float*)d_in[4];
    float* out = (float*)d_out;

    k_prep<<<2 * NT + NPIX / 256, 256>>>(xs, xe, logits);
    k_main<<<MAIN_BLOCKS, 256>>>(gt, mix, out);
}

// round 11
// speedup vs baseline: 1.0084x; 1.0084x over previous
#include <cuda_runtime.h>
#include <math.h>

// ---------------------------------------------------------------------------
// LocalPseudoFeatLoss: B=2, C=19, H=W=128, CH=64, K=7, TOPK=8
// 8 lanes/pixel, coalesced 128B-line slices; pair-symmetric src (sims+counts).
// ---------------------------------------------------------------------------

namespace {
constexpr int NC   = 19;
constexpr int NCP  = 20;     // padded classes
constexpr int HH   = 128;
constexpr int WW   = 128;
constexpr int HWp  = HH * WW;
constexpr int FC   = 64;
constexpr int KK   = 7;
constexpr int K2   = KK * KK;
constexpr int NTOP = 9;
constexpr int NBOT = 8;
constexpr int NPIX = 2 * HWp;
constexpr float EPSV = 1e-8f;
constexpr int FB = FC * 4;    // feature row bytes (256)
constexpr int PB = NCP * 4;   // prob row bytes
constexpr int NT = NPIX / 32; // transpose blocks per tensor (1024)
constexpr int SRC_BLOCKS = 1024;
constexpr int TRG_BLOCKS = 1024;
constexpr int MAIN_BLOCKS = SRC_BLOCKS + TRG_BLOCKS;
}

__device__ float  g_xs[NPIX * FC];     // normalized x_src, pixel-major
__device__ float  g_xe[NPIX * FC];     // normalized x_ema, pixel-major
__device__ float  g_pp[NPIX * NCP];    // softmax(logits), pixel-major, padded
__device__ double g_acc[8];
__device__ int    g_done;
// 0 sum_src_pos  1 cnt_src_pos  2 sum_src_neg  3 n_valid_src
// 4 sum_sim_pos  5 sum_sim_neg  6 cnt_trg

__device__ __forceinline__ float dot4(float4 a, float4 b) {
    float d = a.x * b.x;
    d = fmaf(a.y, b.y, d);
    d = fmaf(a.z, b.z, d);
    d = fmaf(a.w, b.w, d);
    return d;
}

__device__ __forceinline__ unsigned ord_of_f(float f) {
    unsigned b = __float_as_uint(f);
    return b ^ (((unsigned)((int)b >> 31)) | 0x80000000u);
}
__device__ __forceinline__ float f_of_ord(unsigned u) {
    unsigned b = (u & 0x80000000u) ? (u ^ 0x80000000u) : ~u;
    return __uint_as_float(b);
}

// Reduce 8 values across 8 lanes (3 exchange stages).
// On return, lane n of the 8-lane segment holds the total of value n (in v[0]).
__device__ __forceinline__ void tree8x8(float v[8], unsigned mask, int lane) {
    {   bool hi = (lane & 4) != 0;
        #pragma unroll
        for (int j = 0; j < 4; j++) {
            float mine = hi ? v[j] : v[j + 4];
            float kept = hi ? v[j + 4] : v[j];
            v[j] = kept + __shfl_xor_sync(mask, mine, 4);
        } }
    {   bool hi = (lane & 2) != 0;
        #pragma unroll
        for (int j = 0; j < 2; j++) {
            float mine = hi ? v[j] : v[j + 2];
            float kept = hi ? v[j + 2] : v[j];
            v[j] = kept + __shfl_xor_sync(mask, mine, 2);
        } }
    {   bool hi = (lane & 1) != 0;
        float mine = hi ? v[0] : v[1];
        float kept = hi ? v[1] : v[0];
        v[0] = kept + __shfl_xor_sync(mask, mine, 1);
    }
}

// ---- fused prep: blocks [0,NT) transpose xs, [NT,2NT) xe, rest softmax ----
__device__ __forceinline__ void transpose_block(const float* __restrict__ src,
                                                float* __restrict__ dst,
                                                int blk, int t) {
    __shared__ float sm[FC][33];
    int pix0 = blk * 32;
    int b   = pix0 / HWp;
    int hw0 = pix0 - b * HWp;

    int px = t & 31, cb = (t >> 5) * 8;
    const float* sp = src + (size_t)b * FC * HWp + hw0 + px;
    #pragma unroll
    for (int j = 0; j < 8; j++)
        sm[cb + j][px] = sp[(size_t)(cb + j) * HWp];
    __syncthreads();

    int px2 = t >> 3, part = t & 7;
    float v[8];
    float ss = 0.f;
    #pragma unroll
    for (int j = 0; j < 8; j++) {
        v[j] = sm[part * 8 + j][px2];
        ss = fmaf(v[j], v[j], ss);
    }
    #pragma unroll
    for (int o = 4; o; o >>= 1) ss += __shfl_xor_sync(0xffffffffu, ss, o);
    float rn = 1.f / fmaxf(sqrtf(ss), EPSV);
    float4* d = reinterpret_cast<float4*>(dst + (size_t)(pix0 + px2) * FC + part * 8);
    d[0] = make_float4(v[0] * rn, v[1] * rn, v[2] * rn, v[3] * rn);
    d[1] = make_float4(v[4] * rn, v[5] * rn, v[6] * rn, v[7] * rn);
}

__global__ void __launch_bounds__(256)
k_prep(const float* __restrict__ xs, const float* __restrict__ xe,
       const float* __restrict__ logits) {
    int bx = blockIdx.x;
    int t = threadIdx.x;
    if (bx < NT) {
        transpose_block(xs, g_xs, bx, t);
    } else if (bx < 2 * NT) {
        transpose_block(xe, g_xe, bx - NT, t);
    } else {
        int sb = bx - 2 * NT;
        if (sb == 0 && t < 8) g_acc[t] = 0.0;
        if (sb == 0 && t == 8) g_done = 0;
        int pix = sb * 256 + t;
        if (pix >= NPIX) return;
        int b  = pix / HWp;
        int hw = pix - b * HWp;
        const float* lb = logits + (size_t)b * NC * HWp + hw;
        float l[NC];
        float mx = -3.4e38f;
        #pragma unroll
        for (int c = 0; c < NC; c++) {
            l[c] = lb[(size_t)c * HWp];
            mx = fmaxf(mx, l[c]);
        }
        float s = 0.f;
        #pragma unroll
        for (int c = 0; c < NC; c++) { l[c] = expf(l[c] - mx); s += l[c]; }
        float inv = 1.f / s;
        #pragma unroll
        for (int c = 0; c < NC; c++) g_pp[(size_t)pix * NCP + c] = l[c] * inv;
        g_pp[(size_t)pix * NCP + NC] = 0.f;
    }
}

// ---- src path: pair-symmetric sims AND counts over 24 forward neighbors ----
// Pair {p,q} (in-bounds): sum += sim*(wp+wq) to pos/neg; cnt_pos += [eq]*(wp+wq).
// Center: sum_pos += wp, cnt_pos += wp. OOB (class 0): cnt_pos += wp*nOOB*[gc==0].
__device__ __forceinline__ void src_path(const int* __restrict__ gt, int bx) {
    int b  = bx >> 9;
    int tt = bx & 511;                // 16x32 tiles of 8x4
    int h0 = (tt >> 5) << 3;
    int w0 = (tt & 31) << 2;
    int g    = threadIdx.x >> 3;      // 0..31 pixel in tile
    int lane = threadIdx.x & 7;
    unsigned gmask = 0xFFu << (threadIdx.x & 24);
    int h = h0 + (g >> 2), w = w0 + (g & 3);
    int pix = b * HWp + h * WW + w;

    bool interior = (h0 >= 8) && (h0 <= 112) && (w0 >= 4) && (w0 <= 120);

    int gc = gt[pix];
    float wp = (gc != 255) ? 1.f : 0.f;

    float sp = 0.f, sn = 0.f, cp = 0.f, nv = 0.f;

    // coalesced slice: lane covers bytes [lane*16,+16) and [128+lane*16,+16)
    const char* Pl = (const char*)g_xs + (size_t)pix * FB + lane * 16;
    float4 f0 = *(const float4*)Pl;
    float4 f1 = *(const float4*)(Pl + 128);
    const int* Pg = gt + pix;

    if (interior) {
        #pragma unroll
        for (int c = 0; c < 3; c++) {
            #pragma unroll
            for (int n = 0; n < 8; n++) {
                int k  = 25 + c * 8 + n;         // compile-time
                int dy = k / KK - 3;
                int dx = k - (k / KK) * KK - 3;
                int off = dy * WW + dx;
                float4 n0 = *(const float4*)(Pl + (ptrdiff_t)off * FB);
                float4 n1 = *(const float4*)(Pl + (ptrdiff_t)off * FB + 128);
                float s = dot4(f0, n0) + dot4(f1, n1);
                int gq = Pg[off];
                float wgt = wp + ((gq != 255) ? 1.f : 0.f);
                if (gq == gc) { sp = fmaf(wgt, s, sp); cp += wgt; }
                else          { sn = fmaf(wgt, s, sn); }
            }
        }
    } else {
        #pragma unroll 1
        for (int k = 25; k < K2; k++) {
            int dy = k / KK - 3;
            int dx = k - (k / KK) * KK - 3;
            int hn = h + dy, wn = w + dx;
            if ((unsigned)hn < (unsigned)HH && (unsigned)wn < (unsigned)WW) {
                int off = dy * WW + dx;
                float4 n0 = *(const float4*)(Pl + (ptrdiff_t)off * FB);
                float4 n1 = *(const float4*)(Pl + (ptrdiff_t)off * FB + 128);
                float s = dot4(f0, n0) + dot4(f1, n1);
                int gq = Pg[off];
                float wgt = wp + ((gq != 255) ? 1.f : 0.f);
                if (gq == gc) { sp = fmaf(wgt, s, sp); cp += wgt; }
                else          { sn = fmaf(wgt, s, sn); }
            }
        }
    }
    if (lane == 0) {
        sp += wp;        // center pair (k=24): sim = 1, pos
        nv  = wp;
    }

    #pragma unroll
    for (int o = 4; o; o >>= 1) {
        sp += __shfl_xor_sync(gmask, sp, o);
        sn += __shfl_xor_sync(gmask, sn, o);
        cp += __shfl_xor_sync(gmask, cp, o);
        nv += __shfl_xor_sync(gmask, nv, o);
    }
    __shared__ float sa[4];
    if (threadIdx.x < 4) sa[threadIdx.x] = 0.f;
    __syncthreads();
    if (lane == 0) {
        // cp was accumulated identically by all 8 lanes -> /8 (exact: ints)
        float cpFull = cp * 0.125f + wp;          // + center
        if (gc == 0) {                            // OOB neighbors count as class 0
            int y0 = max(h - 3, 0), y1 = min(h + 3, HH - 1);
            int x0 = max(w - 3, 0), x1 = min(w + 3, WW - 1);
            int nIn = (y1 - y0 + 1) * (x1 - x0 + 1);
            cpFull += wp * (float)(K2 - nIn);
        }
        atomicAdd(&sa[0], sp);
        atomicAdd(&sa[1], cpFull);
        atomicAdd(&sa[2], sn);
        atomicAdd(&sa[3], nv);
    }
    __syncthreads();
    if (threadIdx.x == 0) {
        atomicAdd(&g_acc[0], (double)sa[0]);
        atomicAdd(&g_acc[1], (double)sa[1]);
        atomicAdd(&g_acc[2], (double)sa[2]);
        atomicAdd(&g_acc[3], (double)sa[3]);
    }
}

// ---- trg path: sims -> packed-key top-k -> selected cross-probs ----
__device__ __forceinline__ void trg_path(const float* __restrict__ mix, int bx) {
    __shared__ float sm_s[K2][36];   // pad 36: conflict-free tree stores/reads
    __shared__ unsigned long long sel[32][18];
    __shared__ float sred[3];

    int b  = bx >> 9;
    int tt = bx & 511;                // 16x32 tiles of 8x4
    int h0 = (tt >> 5) << 3;
    int w0 = (tt & 31) << 2;
    int g    = threadIdx.x >> 3;      // 0..31 pixel in tile
    int lane = threadIdx.x & 7;
    unsigned gmask = 0xFFu << (threadIdx.x & 24);
    int h = h0 + (g >> 2), w = w0 + (g & 3);
    int pix = b * HWp + h * WW + w;

    bool interior = (h0 >= 8) && (h0 <= 112) && (w0 >= 4) && (w0 <= 120);
    bool act = (1.f - mix[pix]) > 0.5f;

    if (act) {
        const char* Pl = (const char*)g_xe + (size_t)pix * FB + lane * 16;
        float4 f0 = *(const float4*)Pl;
        float4 f1 = *(const float4*)(Pl + 128);
        if (interior) {
            #pragma unroll
            for (int c = 0; c < 6; c++) {
                float sv[8];
                #pragma unroll
                for (int n = 0; n < 8; n++) {
                    int k  = c * 8 + n;
                    int dy = k / KK - 3;
                    int dx = k - (k / KK) * KK - 3;
                    int off = dy * WW + dx;
                    float4 n0 = *(const float4*)(Pl + (ptrdiff_t)off * FB);
                    float4 n1 = *(const float4*)(Pl + (ptrdiff_t)off * FB + 128);
                    sv[n] = dot4(f0, n0) + dot4(f1, n1);
                }
                tree8x8(sv, gmask, lane);
                sm_s[c * 8 + lane][g] = sv[0];
            }
            {   // straggler k = 48
                float4 n0 = *(const float4*)(Pl + (ptrdiff_t)(3 * WW + 3) * FB);
                float4 n1 = *(const float4*)(Pl + (ptrdiff_t)(3 * WW + 3) * FB + 128);
                float pd = dot4(f0, n0) + dot4(f1, n1);
                #pragma unroll
                for (int o = 4; o; o >>= 1)
                    pd += __shfl_xor_sync(gmask, pd, o);
                if (lane == 0) sm_s[48][g] = pd;
            }
        } else {
            int k = 0;
            #pragma unroll 1
            for (int ky = 0; ky < KK; ky++) {
                int hn = h + ky - 3;
                bool rv = (unsigned)hn < (unsigned)HH;
                int hc = min(max(hn, 0), HH - 1);
                #pragma unroll
                for (int kx = 0; kx < KK; kx++, k++) {
                    int wn = w + kx - 3;
                    bool ok = rv && ((unsigned)wn < (unsigned)WW);
                    int wc = min(max(wn, 0), WW - 1);
                    int pn = b * HWp + hc * WW + wc;
                    const char* Pn = (const char*)g_xe + (size_t)pn * FB + lane * 16;
                    float4 n0 = *(const float4*)Pn;
                    float4 n1 = *(const float4*)(Pn + 128);
                    float pd = dot4(f0, n0) + dot4(f1, n1);
                    #pragma unroll
                    for (int o = 4; o; o >>= 1)
                        pd += __shfl_xor_sync(gmask, pd, o);
                    if (lane == 0) sm_s[k][g] = ok ? pd : 0.f;
                }
            }
        }
    }
    if (threadIdx.x < 3) sred[threadIdx.x] = 0.f;
    __syncthreads();

    // phase 2a: selection on packed keys (64 threads, 32 top + 32 bottom)
    if (threadIdx.x < 64) {
        int t = threadIdx.x;
        int q2 = t & 31;
        int h2 = h0 + (q2 >> 2), w2 = w0 + (q2 & 3);
        int p2 = b * HWp + h2 * WW + w2;
        if ((1.f - mix[p2]) > 0.5f) {
            if (t < 32) {
                unsigned long long key[NTOP];
                #pragma unroll
                for (int i = 0; i < NTOP; i++) key[i] = 0ull;
                #pragma unroll 1
                for (int k = 0; k < K2; k++) {
                    unsigned long long kk =
                        ((unsigned long long)ord_of_f(sm_s[k][q2]) << 8)
                        | (unsigned)(63 - k);
                    if (kk > key[NTOP - 1]) {
                        #pragma unroll
                        for (int i = 0; i < NTOP; i++)
                            if (kk > key[i]) {
                                unsigned long long x = key[i]; key[i] = kk; kk = x;
                            }
                    }
                }
                #pragma unroll
                for (int i = 0; i < NTOP; i++) sel[q2][i] = key[i];
            } else {
                unsigned long long key[NBOT];
                #pragma unroll
                for (int i = 0; i < NBOT; i++) key[i] = ~0ull;
                #pragma unroll 1
                for (int k = 0; k < K2; k++) {
                    unsigned long long kk =
                        ((unsigned long long)ord_of_f(sm_s[k][q2]) << 8)
                        | (unsigned)k;
                    if (kk < key[NBOT - 1]) {
                        #pragma unroll
                        for (int i = 0; i < NBOT; i++)
                            if (kk < key[i]) {
                                unsigned long long x = key[i]; key[i] = kk; kk = x;
                            }
                    }
                }
                #pragma unroll
                for (int i = 0; i < NBOT; i++) sel[q2][NTOP + i] = key[i];
            }
        }
    }
    __syncthreads();

    // phase 2b: 17 selected prob dots per pixel (8 lanes/pixel)
    float ssp = 0.f, ssn = 0.f, cnt = 0.f;
    if (act) {
        if (lane == 0) cnt = 1.f;
        const float4* A = reinterpret_cast<const float4*>(g_pp + (size_t)pix * NCP);
        float4 A0 = A[0], A1 = A[1], A2 = A[2], A3 = A[3], A4 = A[4];
        #pragma unroll 1
        for (int tid = lane; tid < NTOP + NBOT; tid += 8) {
            unsigned long long kk = sel[g][tid];
            bool isTop = tid < NTOP;
            int k = isTop ? (63 - (int)(kk & 63u)) : (int)(kk & 63u);
            float val = f_of_ord((unsigned)(kk >> 8));
            int dy = ((k * 9363) >> 16) - 3;
            int dx = k - (dy + 3) * KK - 3;
            int hn = h + dy, wn = w + dx;
            float cpv = 1.f / 19.f;
            if ((unsigned)hn < (unsigned)HH && (unsigned)wn < (unsigned)WW) {
                const float4* Bv = reinterpret_cast<const float4*>(
                    g_pp + (size_t)(pix + dy * WW + dx) * NCP);
                float d2 = dot4(A0, Bv[0]);
                d2 += dot4(A1, Bv[1]);
                d2 += dot4(A2, Bv[2]);
                d2 += dot4(A3, Bv[3]);
                d2 += dot4(A4, Bv[4]);
                cpv = d2;
            }
            if (isTop) ssp = fmaf(val, -cpv, ssp);
            else       ssn += (1.f - val) * (-(1.f - cpv));
        }
    }
    #pragma unroll
    for (int o = 16; o; o >>= 1) {
        ssp += __shfl_xor_sync(0xffffffffu, ssp, o);
        ssn += __shfl_xor_sync(0xffffffffu, ssn, o);
        cnt += __shfl_xor_sync(0xffffffffu, cnt, o);
    }
    if ((threadIdx.x & 31) == 0) {
        atomicAdd(&sred[0], ssp);
        atomicAdd(&sred[1], ssn);
        atomicAdd(&sred[2], cnt);
    }
    __syncthreads();
    if (threadIdx.x == 0) {
        atomicAdd(&g_acc[4], (double)sred[0]);
        atomicAdd(&g_acc[5], (double)sred[1]);
        atomicAdd(&g_acc[6], (double)sred[2]);
    }
}

// ---- merged main: interleaved src/trg blocks + last-block finalize ----
__global__ void __launch_bounds__(256, 5)
k_main(const int* __restrict__ gt, const float* __restrict__ mix,
       float* __restrict__ out) {
    int bx = blockIdx.x;
    if (bx & 1) trg_path(mix, bx >> 1);
    else        src_path(gt, bx >> 1);

    __shared__ bool isLast;
    if (threadIdx.x == 0) {
        __threadfence();
        int prev = atomicAdd(&g_done, 1);
        isLast = (prev == MAIN_BLOCKS - 1);
    }
    __syncthreads();
    if (isLast && threadIdx.x == 0) {
        double cntP = g_acc[1];
        double cntN = 49.0 * g_acc[3] - cntP;
        double src_pos = g_acc[0] / fmax(cntP, 1.0);
        double src_neg = g_acc[2] / fmax(cntN, 1.0);
        double sim_pos = g_acc[4] / fmax((double)NTOP * g_acc[6], 1.0);
        double sim_neg = g_acc[5] / fmax((double)NBOT * g_acc[6], 1.0);
        out[0] = (float)(-src_pos);
        out[1] = (float)( src_neg);
        out[2] = (float)( sim_pos);
        out[3] = (float)( sim_neg);
    }
}

extern "C" void kernel_launch(void* const* d_in, const int* in_sizes, int n_in,
                              void* d_out, int out_size) {
    (void)in_sizes; (void)n_in; (void)out_size;
    const float* logits = (const float*)d_in[0];
    const int*   gt     = (const int*)d_in[1];
    const float* xe     = (const float*)d_in[2];
    const float* xs     = (const float*)d_in[3];
    const float* mix    = (const float*)d_in[4];
    float* out = (float*)d_out;

    k_prep<<<2 * NT + NPIX / 256, 256>>>(xs, xe, logits);
    k_main<<<MAIN_BLOCKS, 256>>>(gt, mix, out);
}

// round 12
// speedup vs baseline: 1.3553x; 1.3440x over previous
#include <cuda_runtime.h>
#include <math.h>

// ---------------------------------------------------------------------------
// LocalPseudoFeatLoss: B=2, C=19, H=W=128, CH=64, K=7, TOPK=8
// 8 lanes/pixel coalesced slices; pair-symmetric src; compacted trg worklist
// (interior actives from front of g_wl, border actives from back).
// ---------------------------------------------------------------------------

namespace {
constexpr int NC   = 19;
constexpr int NCP  = 20;     // padded classes
constexpr int HH   = 128;
constexpr int WW   = 128;
constexpr int HWp  = HH * WW;
constexpr int FC   = 64;
constexpr int KK   = 7;
constexpr int K2   = KK * KK;
constexpr int NTOP = 9;
constexpr int NBOT = 8;
constexpr int NPIX = 2 * HWp;
constexpr float EPSV = 1e-8f;
constexpr int FB = FC * 4;    // feature row bytes (256)
constexpr int PB = NCP * 4;   // prob row bytes
constexpr int NT = NPIX / 32;      // transpose blocks per tensor (1024)
constexpr int NSOFT = NPIX / 256;  // softmax blocks (128)
constexpr int NCOMP = NPIX / 256;  // compaction blocks (128)
constexpr int SRC_BLOCKS  = 1024;
constexpr int TRGI_BLOCKS = (2 * 122 * 122 + 31) / 32;   // 931 (worst case)
constexpr int TRGB_BLOCKS = (2 * (HH * WW - 122 * 122) + 31) / 32;  // 94
constexpr int MAIN_BLOCKS = SRC_BLOCKS + TRGI_BLOCKS + TRGB_BLOCKS; // 2049
}

__device__ float  g_xs[NPIX * FC];     // normalized x_src, pixel-major
__device__ float  g_xe[NPIX * FC];     // normalized x_ema, pixel-major
__device__ float  g_pp[NPIX * NCP];    // softmax(logits), pixel-major, padded
__device__ int    g_wl[NPIX];          // worklist: interior front, border back
__device__ int    g_nint = 0;          // reset by k_main finalize
__device__ int    g_nbrd = 0;
__device__ double g_acc[8];
__device__ int    g_done;
// 0 sum_src_pos  1 cnt_src_pos  2 sum_src_neg  3 n_valid_src
// 4 sum_sim_pos  5 sum_sim_neg  6 cnt_trg

__device__ __forceinline__ float dot4(float4 a, float4 b) {
    float d = a.x * b.x;
    d = fmaf(a.y, b.y, d);
    d = fmaf(a.z, b.z, d);
    d = fmaf(a.w, b.w, d);
    return d;
}

__device__ __forceinline__ unsigned ord_of_f(float f) {
    unsigned b = __float_as_uint(f);
    return b ^ (((unsigned)((int)b >> 31)) | 0x80000000u);
}
__device__ __forceinline__ float f_of_ord(unsigned u) {
    unsigned b = (u & 0x80000000u) ? (u ^ 0x80000000u) : ~u;
    return __uint_as_float(b);
}

// Reduce 8 values across 8 lanes (3 exchange stages); lane n gets total n.
__device__ __forceinline__ void tree8x8(float v[8], unsigned mask, int lane) {
    {   bool hi = (lane & 4) != 0;
        #pragma unroll
        for (int j = 0; j < 4; j++) {
            float mine = hi ? v[j] : v[j + 4];
            float kept = hi ? v[j + 4] : v[j];
            v[j] = kept + __shfl_xor_sync(mask, mine, 4);
        } }
    {   bool hi = (lane & 2) != 0;
        #pragma unroll
        for (int j = 0; j < 2; j++) {
            float mine = hi ? v[j] : v[j + 2];
            float kept = hi ? v[j + 2] : v[j];
            v[j] = kept + __shfl_xor_sync(mask, mine, 2);
        } }
    {   bool hi = (lane & 1) != 0;
        float mine = hi ? v[0] : v[1];
        float kept = hi ? v[1] : v[0];
        v[0] = kept + __shfl_xor_sync(mask, mine, 1);
    }
}

// ---- prep: transpose xs/xe + softmax + trg-active compaction ----
__device__ __forceinline__ void transpose_block(const float* __restrict__ src,
                                                float* __restrict__ dst,
                                                int blk, int t) {
    __shared__ float sm[FC][33];
    int pix0 = blk * 32;
    int b   = pix0 / HWp;
    int hw0 = pix0 - b * HWp;

    int px = t & 31, cb = (t >> 5) * 8;
    const float* sp = src + (size_t)b * FC * HWp + hw0 + px;
    #pragma unroll
    for (int j = 0; j < 8; j++)
        sm[cb + j][px] = sp[(size_t)(cb + j) * HWp];
    __syncthreads();

    int px2 = t >> 3, part = t & 7;
    float v[8];
    float ss = 0.f;
    #pragma unroll
    for (int j = 0; j < 8; j++) {
        v[j] = sm[part * 8 + j][px2];
        ss = fmaf(v[j], v[j], ss);
    }
    #pragma unroll
    for (int o = 4; o; o >>= 1) ss += __shfl_xor_sync(0xffffffffu, ss, o);
    float rn = 1.f / fmaxf(sqrtf(ss), EPSV);
    float4* d = reinterpret_cast<float4*>(dst + (size_t)(pix0 + px2) * FC + part * 8);
    d[0] = make_float4(v[0] * rn, v[1] * rn, v[2] * rn, v[3] * rn);
    d[1] = make_float4(v[4] * rn, v[5] * rn, v[6] * rn, v[7] * rn);
}

__global__ void __launch_bounds__(256)
k_prep(const float* __restrict__ xs, const float* __restrict__ xe,
       const float* __restrict__ logits, const float* __restrict__ mix) {
    int bx = blockIdx.x;
    int t = threadIdx.x;
    if (bx < NT) {
        transpose_block(xs, g_xs, bx, t);
    } else if (bx < 2 * NT) {
        transpose_block(xe, g_xe, bx - NT, t);
    } else if (bx < 2 * NT + NSOFT) {
        int sb = bx - 2 * NT;
        if (sb == 0 && t < 8) g_acc[t] = 0.0;
        if (sb == 0 && t == 8) g_done = 0;
        int pix = sb * 256 + t;
        int b  = pix / HWp;
        int hw = pix - b * HWp;
        const float* lb = logits + (size_t)b * NC * HWp + hw;
        float l[NC];
        float mx = -3.4e38f;
        #pragma unroll
        for (int c = 0; c < NC; c++) {
            l[c] = lb[(size_t)c * HWp];
            mx = fmaxf(mx, l[c]);
        }
        float s = 0.f;
        #pragma unroll
        for (int c = 0; c < NC; c++) { l[c] = expf(l[c] - mx); s += l[c]; }
        float inv = 1.f / s;
        #pragma unroll
        for (int c = 0; c < NC; c++) g_pp[(size_t)pix * NCP + c] = l[c] * inv;
        g_pp[(size_t)pix * NCP + NC] = 0.f;
    } else {
        // compaction: active target pixels -> worklist (interior / border)
        int cbk = bx - 2 * NT - NSOFT;
        int pix = cbk * 256 + t;
        bool a = (1.f - mix[pix]) > 0.5f;
        int hw = pix & (HWp - 1);
        int h = hw >> 7, w = hw & 127;
        bool inter = (h >= 3) && (h <= 124) && (w >= 3) && (w <= 124);
        unsigned mI = __ballot_sync(0xffffffffu, a && inter);
        unsigned mB = __ballot_sync(0xffffffffu, a && !inter);
        int lane = t & 31;
        int bI = 0, bB = 0;
        if (lane == 0) {
            if (mI) bI = atomicAdd(&g_nint, __popc(mI));
            if (mB) bB = atomicAdd(&g_nbrd, __popc(mB));
        }
        bI = __shfl_sync(0xffffffffu, bI, 0);
        bB = __shfl_sync(0xffffffffu, bB, 0);
        unsigned below = (1u << lane) - 1u;
        if (a && inter)  g_wl[bI + __popc(mI & below)] = pix;
        if (a && !inter) g_wl[NPIX - 1 - (bB + __popc(mB & below))] = pix;
    }
}

// ---- src path: pair-symmetric sims AND counts over 24 forward neighbors ----
__device__ __forceinline__ void src_path(const int* __restrict__ gt, int bx) {
    int b  = bx >> 9;
    int tt = bx & 511;                // 16x32 tiles of 8x4
    int h0 = (tt >> 5) << 3;
    int w0 = (tt & 31) << 2;
    int g    = threadIdx.x >> 3;      // 0..31 pixel in tile
    int lane = threadIdx.x & 7;
    unsigned gmask = 0xFFu << (threadIdx.x & 24);
    int h = h0 + (g >> 2), w = w0 + (g & 3);
    int pix = b * HWp + h * WW + w;

    bool interior = (h0 >= 8) && (h0 <= 112) && (w0 >= 4) && (w0 <= 120);

    int gc = gt[pix];
    float wp = (gc != 255) ? 1.f : 0.f;

    float sp = 0.f, sn = 0.f, cp = 0.f, nv = 0.f;

    const char* Pl = (const char*)g_xs + (size_t)pix * FB + lane * 16;
    float4 f0 = *(const float4*)Pl;
    float4 f1 = *(const float4*)(Pl + 128);
    const int* Pg = gt + pix;

    if (interior) {
        #pragma unroll
        for (int c = 0; c < 3; c++) {
            #pragma unroll
            for (int n = 0; n < 8; n++) {
                int k  = 25 + c * 8 + n;         // compile-time
                int dy = k / KK - 3;
                int dx = k - (k / KK) * KK - 3;
                int off = dy * WW + dx;
                float4 n0 = *(const float4*)(Pl + (ptrdiff_t)off * FB);
                float4 n1 = *(const float4*)(Pl + (ptrdiff_t)off * FB + 128);
                float s = dot4(f0, n0) + dot4(f1, n1);
                int gq = Pg[off];
                float wgt = wp + ((gq != 255) ? 1.f : 0.f);
                if (gq == gc) { sp = fmaf(wgt, s, sp); cp += wgt; }
                else          { sn = fmaf(wgt, s, sn); }
            }
        }
    } else {
        #pragma unroll 1
        for (int k = 25; k < K2; k++) {
            int dy = k / KK - 3;
            int dx = k - (k / KK) * KK - 3;
            int hn = h + dy, wn = w + dx;
            if ((unsigned)hn < (unsigned)HH && (unsigned)wn < (unsigned)WW) {
                int off = dy * WW + dx;
                float4 n0 = *(const float4*)(Pl + (ptrdiff_t)off * FB);
                float4 n1 = *(const float4*)(Pl + (ptrdiff_t)off * FB + 128);
                float s = dot4(f0, n0) + dot4(f1, n1);
                int gq = Pg[off];
                float wgt = wp + ((gq != 255) ? 1.f : 0.f);
                if (gq == gc) { sp = fmaf(wgt, s, sp); cp += wgt; }
                else          { sn = fmaf(wgt, s, sn); }
            }
        }
    }
    if (lane == 0) {
        sp += wp;        // center pair (k=24): sim = 1, pos
        nv  = wp;
    }

    #pragma unroll
    for (int o = 4; o; o >>= 1) {
        sp += __shfl_xor_sync(gmask, sp, o);
        sn += __shfl_xor_sync(gmask, sn, o);
        cp += __shfl_xor_sync(gmask, cp, o);
        nv += __shfl_xor_sync(gmask, nv, o);
    }
    __shared__ float sa[4];
    if (threadIdx.x < 4) sa[threadIdx.x] = 0.f;
    __syncthreads();
    if (lane == 0) {
        float cpFull = cp * 0.125f + wp;          // lanes identical -> /8 exact
        if (gc == 0) {                            // OOB neighbors count as class 0
            int y0 = max(h - 3, 0), y1 = min(h + 3, HH - 1);
            int x0 = max(w - 3, 0), x1 = min(w + 3, WW - 1);
            int nIn = (y1 - y0 + 1) * (x1 - x0 + 1);
            cpFull += wp * (float)(K2 - nIn);
        }
        atomicAdd(&sa[0], sp);
        atomicAdd(&sa[1], cpFull);
        atomicAdd(&sa[2], sn);
        atomicAdd(&sa[3], nv);
    }
    __syncthreads();
    if (threadIdx.x == 0) {
        atomicAdd(&g_acc[0], (double)sa[0]);
        atomicAdd(&g_acc[1], (double)sa[1]);
        atomicAdd(&g_acc[2], (double)sa[2]);
        atomicAdd(&g_acc[3], (double)sa[3]);
    }
}

// ---- trg interior: worklist entries, branch-free fast path everywhere ----
__device__ __forceinline__ void trg_int(int bx) {
    __shared__ float sm_s[K2][36];
    __shared__ unsigned long long sel[32][18];
    __shared__ float sred[3];

    int nInt = g_nint;
    int base = bx * 32;
    if (base >= nInt) return;       // idle block (uniform)

    int g    = threadIdx.x >> 3;
    int lane = threadIdx.x & 7;
    unsigned gmask = 0xFFu << (threadIdx.x & 24);
    int idx = base + g;
    bool act = idx < nInt;
    int pix = g_wl[act ? idx : base];

    if (act) {
        const char* Pl = (const char*)g_xe + (size_t)pix * FB + lane * 16;
        float4 f0 = *(const float4*)Pl;
        float4 f1 = *(const float4*)(Pl + 128);
        #pragma unroll
        for (int c = 0; c < 6; c++) {
            float sv[8];
            #pragma unroll
            for (int n = 0; n < 8; n++) {
                int k  = c * 8 + n;
                int dy = k / KK - 3;
                int dx = k - (k / KK) * KK - 3;
                int off = dy * WW + dx;
                float4 n0 = *(const float4*)(Pl + (ptrdiff_t)off * FB);
                float4 n1 = *(const float4*)(Pl + (ptrdiff_t)off * FB + 128);
                sv[n] = dot4(f0, n0) + dot4(f1, n1);
            }
            tree8x8(sv, gmask, lane);
            sm_s[c * 8 + lane][g] = sv[0];
        }
        {   // straggler k = 48
            float4 n0 = *(const float4*)(Pl + (ptrdiff_t)(3 * WW + 3) * FB);
            float4 n1 = *(const float4*)(Pl + (ptrdiff_t)(3 * WW + 3) * FB + 128);
            float pd = dot4(f0, n0) + dot4(f1, n1);
            #pragma unroll
            for (int o = 4; o; o >>= 1)
                pd += __shfl_xor_sync(gmask, pd, o);
            if (lane == 0) sm_s[48][g] = pd;
        }
    }
    if (threadIdx.x < 3) sred[threadIdx.x] = 0.f;
    __syncthreads();

    // phase 2a: selection (64 threads, 32 top + 32 bottom)
    if (threadIdx.x < 64) {
        int t = threadIdx.x;
        int q2 = t & 31;
        if (base + q2 < nInt) {
            if (t < 32) {
                unsigned long long key[NTOP];
                #pragma unroll
                for (int i = 0; i < NTOP; i++) key[i] = 0ull;
                #pragma unroll 1
                for (int k = 0; k < K2; k++) {
                    unsigned long long kk =
                        ((unsigned long long)ord_of_f(sm_s[k][q2]) << 8)
                        | (unsigned)(63 - k);
                    if (kk > key[NTOP - 1]) {
                        #pragma unroll
                        for (int i = 0; i < NTOP; i++)
                            if (kk > key[i]) {
                                unsigned long long x = key[i]; key[i] = kk; kk = x;
                            }
                    }
                }
                #pragma unroll
                for (int i = 0; i < NTOP; i++) sel[q2][i] = key[i];
            } else {
                unsigned long long key[NBOT];
                #pragma unroll
                for (int i = 0; i < NBOT; i++) key[i] = ~0ull;
                #pragma unroll 1
                for (int k = 0; k < K2; k++) {
                    unsigned long long kk =
                        ((unsigned long long)ord_of_f(sm_s[k][q2]) << 8)
                        | (unsigned)k;
                    if (kk < key[NBOT - 1]) {
                        #pragma unroll
                        for (int i = 0; i < NBOT; i++)
                            if (kk < key[i]) {
                                unsigned long long x = key[i]; key[i] = kk; kk = x;
                            }
                    }
                }
                #pragma unroll
                for (int i = 0; i < NBOT; i++) sel[q2][NTOP + i] = key[i];
            }
        }
    }
    __syncthreads();

    // phase 2b: 17 selected prob dots (interior: no bounds checks at all)
    float ssp = 0.f, ssn = 0.f, cnt = 0.f;
    if (act) {
        if (lane == 0) cnt = 1.f;
        const float4* A = reinterpret_cast<const float4*>(g_pp + (size_t)pix * NCP);
        float4 A0 = A[0], A1 = A[1], A2 = A[2], A3 = A[3], A4 = A[4];
        #pragma unroll 1
        for (int tid = lane; tid < NTOP + NBOT; tid += 8) {
            unsigned long long kk = sel[g][tid];
            bool isTop = tid < NTOP;
            int k = isTop ? (63 - (int)(kk & 63u)) : (int)(kk & 63u);
            float val = f_of_ord((unsigned)(kk >> 8));
            int dy = ((k * 9363) >> 16) - 3;
            int dx = k - (dy + 3) * KK - 3;
            const float4* Bv = reinterpret_cast<const float4*>(
                g_pp + (size_t)(pix + dy * WW + dx) * NCP);
            float cpv = dot4(A0, Bv[0]);
            cpv += dot4(A1, Bv[1]);
            cpv += dot4(A2, Bv[2]);
            cpv += dot4(A3, Bv[3]);
            cpv += dot4(A4, Bv[4]);
            if (isTop) ssp = fmaf(val, -cpv, ssp);
            else       ssn += (1.f - val) * (-(1.f - cpv));
        }
    }
    #pragma unroll
    for (int o = 16; o; o >>= 1) {
        ssp += __shfl_xor_sync(0xffffffffu, ssp, o);
        ssn += __shfl_xor_sync(0xffffffffu, ssn, o);
        cnt += __shfl_xor_sync(0xffffffffu, cnt, o);
    }
    if ((threadIdx.x & 31) == 0) {
        atomicAdd(&sred[0], ssp);
        atomicAdd(&sred[1], ssn);
        atomicAdd(&sred[2], cnt);
    }
    __syncthreads();
    if (threadIdx.x == 0) {
        atomicAdd(&g_acc[4], (double)sred[0]);
        atomicAdd(&g_acc[5], (double)sred[1]);
        atomicAdd(&g_acc[6], (double)sred[2]);
    }
}

// ---- trg border: worklist entries from back, bounds-checked path ----
__device__ __forceinline__ void trg_brd(int bx) {
    __shared__ float sm_s[K2][36];
    __shared__ unsigned long long sel[32][18];
    __shared__ float sred[3];

    int nBrd = g_nbrd;
    int base = bx * 32;
    if (base >= nBrd) return;

    int g    = threadIdx.x >> 3;
    int lane = threadIdx.x & 7;
    unsigned gmask = 0xFFu << (threadIdx.x & 24);
    int idx = base + g;
    bool act = idx < nBrd;
    int pix = g_wl[NPIX - 1 - (act ? idx : base)];
    int hw = pix & (HWp - 1);
    int h = hw >> 7, w = hw & 127;

    if (act) {
        const char* Pl = (const char*)g_xe + (size_t)pix * FB + lane * 16;
        float4 f0 = *(const float4*)Pl;
        float4 f1 = *(const float4*)(Pl + 128);
        int k = 0;
        #pragma unroll 1
        for (int ky = 0; ky < KK; ky++) {
            int hn = h + ky - 3;
            bool rv = (unsigned)hn < (unsigned)HH;
            int hc = min(max(hn, 0), HH - 1);
            #pragma unroll
            for (int kx = 0; kx < KK; kx++, k++) {
                int wn = w + kx - 3;
                bool ok = rv && ((unsigned)wn < (unsigned)WW);
                int wc = min(max(wn, 0), WW - 1);
                int pn = (pix & ~(HWp - 1)) + hc * WW + wc;
                const char* Pn = (const char*)g_xe + (size_t)pn * FB + lane * 16;
                float4 n0 = *(const float4*)Pn;
                float4 n1 = *(const float4*)(Pn + 128);
                float pd = dot4(f0, n0) + dot4(f1, n1);
                #pragma unroll
                for (int o = 4; o; o >>= 1)
                    pd += __shfl_xor_sync(gmask, pd, o);
                if (lane == 0) sm_s[k][g] = ok ? pd : 0.f;
            }
        }
    }
    if (threadIdx.x < 3) sred[threadIdx.x] = 0.f;
    __syncthreads();

    if (threadIdx.x < 64) {
        int t = threadIdx.x;
        int q2 = t & 31;
        if (base + q2 < nBrd) {
            if (t < 32) {
                unsigned long long key[NTOP];
                #pragma unroll
                for (int i = 0; i < NTOP; i++) key[i] = 0ull;
                #pragma unroll 1
                for (int k = 0; k < K2; k++) {
                    unsigned long long kk =
                        ((unsigned long long)ord_of_f(sm_s[k][q2]) << 8)
                        | (unsigned)(63 - k);
                    if (kk > key[NTOP - 1]) {
                        #pragma unroll
                        for (int i = 0; i < NTOP; i++)
                            if (kk > key[i]) {
                                unsigned long long x = key[i]; key[i] = kk; kk = x;
                            }
                    }
                }
                #pragma unroll
                for (int i = 0; i < NTOP; i++) sel[q2][i] = key[i];
            } else {
                unsigned long long key[NBOT];
                #pragma unroll
                for (int i = 0; i < NBOT; i++) key[i] = ~0ull;
                #pragma unroll 1
                for (int k = 0; k < K2; k++) {
                    unsigned long long kk =
                        ((unsigned long long)ord_of_f(sm_s[k][q2]) << 8)
                        | (unsigned)k;
                    if (kk < key[NBOT - 1]) {
                        #pragma unroll
                        for (int i = 0; i < NBOT; i++)
                            if (kk < key[i]) {
                                unsigned long long x = key[i]; key[i] = kk; kk = x;
                            }
                    }
                }
                #pragma unroll
                for (int i = 0; i < NBOT; i++) sel[q2][NTOP + i] = key[i];
            }
        }
    }
    __syncthreads();

    float ssp = 0.f, ssn = 0.f, cnt = 0.f;
    if (act) {
        if (lane == 0) cnt = 1.f;
        const float4* A = reinterpret_cast<const float4*>(g_pp + (size_t)pix * NCP);
        float4 A0 = A[0], A1 = A[1], A2 = A[2], A3 = A[3], A4 = A[4];
        #pragma unroll 1
        for (int tid = lane; tid < NTOP + NBOT; tid += 8) {
            unsigned long long kk = sel[g][tid];
            bool isTop = tid < NTOP;
            int k = isTop ? (63 - (int)(kk & 63u)) : (int)(kk & 63u);
            float val = f_of_ord((unsigned)(kk >> 8));
            int dy = ((k * 9363) >> 16) - 3;
            int dx = k - (dy + 3) * KK - 3;
            int hn = h + dy, wn = w + dx;
            float cpv = 1.f / 19.f;
            if ((unsigned)hn < (unsigned)HH && (unsigned)wn < (unsigned)WW) {
                const float4* Bv = reinterpret_cast<const float4*>(
                    g_pp + (size_t)(pix + dy * WW + dx) * NCP);
                float d2 = dot4(A0, Bv[0]);
                d2 += dot4(A1, Bv[1]);
                d2 += dot4(A2, Bv[2]);
                d2 += dot4(A3, Bv[3]);
                d2 += dot4(A4, Bv[4]);
                cpv = d2;
            }
            if (isTop) ssp = fmaf(val, -cpv, ssp);
            else       ssn += (1.f - val) * (-(1.f - cpv));
        }
    }
    #pragma unroll
    for (int o = 16; o; o >>= 1) {
        ssp += __shfl_xor_sync(0xffffffffu, ssp, o);
        ssn += __shfl_xor_sync(0xffffffffu, ssn, o);
        cnt += __shfl_xor_sync(0xffffffffu, cnt, o);
    }
    if ((threadIdx.x & 31) == 0) {
        atomicAdd(&sred[0], ssp);
        atomicAdd(&sred[1], ssn);
        atomicAdd(&sred[2], cnt);
    }
    __syncthreads();
    if (threadIdx.x == 0) {
        atomicAdd(&g_acc[4], (double)sred[0]);
        atomicAdd(&g_acc[5], (double)sred[1]);
        atomicAdd(&g_acc[6], (double)sred[2]);
    }
}

// ---- merged main: border + interleaved src/trg-int + finalize/reset ----
__global__ void __launch_bounds__(256, 5)
k_main(const int* __restrict__ gt, float* __restrict__ out) {
    int bx = blockIdx.x;
    if (bx < TRGB_BLOCKS) {
        trg_brd(bx);
    } else {
        int r = bx - TRGB_BLOCKS;
        if (r < 2 * TRGI_BLOCKS) {
            if (r & 1) trg_int(r >> 1);
            else       src_path(gt, r >> 1);
        } else {
            src_path(gt, TRGI_BLOCKS + (r - 2 * TRGI_BLOCKS));
        }
    }

    __shared__ bool isLast;
    if (threadIdx.x == 0) {
        __threadfence();
        int prev = atomicAdd(&g_done, 1);
        isLast = (prev == MAIN_BLOCKS - 1);
    }
    __syncthreads();
    if (isLast && threadIdx.x == 0) {
        double cntP = g_acc[1];
        double cntN = 49.0 * g_acc[3] - cntP;
        double src_pos = g_acc[0] / fmax(cntP, 1.0);
        double src_neg = g_acc[2] / fmax(cntN, 1.0);
        double sim_pos = g_acc[4] / fmax((double)NTOP * g_acc[6], 1.0);
        double sim_neg = g_acc[5] / fmax((double)NBOT * g_acc[6], 1.0);
        out[0] = (float)(-src_pos);
        out[1] = (float)( src_neg);
        out[2] = (float)( sim_pos);
        out[3] = (float)( sim_neg);
        g_nint = 0;          // reset for next graph replay
        g_nbrd = 0;
    }
}

extern "C" void kernel_launch(void* const* d_in, const int* in_sizes, int n_in,
                              void* d_out, int out_size) {
    (void)in_sizes; (void)n_in; (void)out_size;
    const float* logits = (const float*)d_in[0];
    const int*   gt     = (const int*)d_in[1];
    const float* xe     = (const float*)d_in[2];
    const float* xs     = (const float*)d_in[3];
    const float* mix    = (const float*)d_in[4];
    float* out = (float*)d_out;

    k_prep<<<2 * NT + NSOFT + NCOMP, 256>>>(xs, xe, logits, mix);
    k_main<<<MAIN_BLOCKS, 256>>>(gt, out);
}

// round 13
// speedup vs baseline: 1.5841x; 1.1688x over previous
#include <cuda_runtime.h>
#include <cuda_fp16.h>
#include <math.h>

// ---------------------------------------------------------------------------
// LocalPseudoFeatLoss: B=2, C=19, H=W=128, CH=64, K=7, TOPK=8
// fp16 normalized features (128B rows, 1 line per 8-lane group load),
// HFMA2 dots + fp32 reduction; pair-symmetric src; compacted trg worklist.
// ---------------------------------------------------------------------------

namespace {
constexpr int NC   = 19;
constexpr int NCP  = 20;     // padded classes
constexpr int HH   = 128;
constexpr int WW   = 128;
constexpr int HWp  = HH * WW;
constexpr int FC   = 64;
constexpr int KK   = 7;
constexpr int K2   = KK * KK;
constexpr int NTOP = 9;
constexpr int NBOT = 8;
constexpr int NPIX = 2 * HWp;
constexpr float EPSV = 1e-8f;
constexpr int FBH = FC * 2;   // fp16 feature row bytes (128)
constexpr int NT = NPIX / 32;      // transpose blocks per tensor (1024)
constexpr int NSOFT = NPIX / 256;  // softmax blocks (128)
constexpr int NCOMP = NPIX / 256;  // compaction blocks (128)
constexpr int SRC_BLOCKS  = 1024;
constexpr int TRGI_BLOCKS = (2 * 122 * 122 + 31) / 32;   // 931 (worst case)
constexpr int TRGB_BLOCKS = (2 * (HH * WW - 122 * 122) + 31) / 32;  // 94
constexpr int MAIN_BLOCKS = SRC_BLOCKS + TRGI_BLOCKS + TRGB_BLOCKS; // 2049
}

__device__ __half  g_xs[NPIX * FC];    // normalized x_src, fp16 pixel-major
__device__ __half  g_xe[NPIX * FC];    // normalized x_ema, fp16 pixel-major
__device__ float   g_pp[NPIX * NCP];   // softmax(logits), fp32, padded
__device__ int     g_wl[NPIX];         // worklist: interior front, border back
__device__ int     g_nint = 0;         // reset by k_main finalize
__device__ int     g_nbrd = 0;
__device__ double  g_acc[8];
__device__ int     g_done;
// 0 sum_src_pos  1 cnt_src_pos  2 sum_src_neg  3 n_valid_src
// 4 sum_sim_pos  5 sum_sim_neg  6 cnt_trg

__device__ __forceinline__ float dot4(float4 a, float4 b) {
    float d = a.x * b.x;
    d = fmaf(a.y, b.y, d);
    d = fmaf(a.z, b.z, d);
    d = fmaf(a.w, b.w, d);
    return d;
}

// 8-channel fp16 dot: 4 HFMA2 in half2, fp32 horizontal combine.
__device__ __forceinline__ float hdot8(uint4 a, uint4 b) {
    __half2 a0 = *reinterpret_cast<const __half2*>(&a.x);
    __half2 a1 = *reinterpret_cast<const __half2*>(&a.y);
    __half2 a2 = *reinterpret_cast<const __half2*>(&a.z);
    __half2 a3 = *reinterpret_cast<const __half2*>(&a.w);
    __half2 b0 = *reinterpret_cast<const __half2*>(&b.x);
    __half2 b1 = *reinterpret_cast<const __half2*>(&b.y);
    __half2 b2 = *reinterpret_cast<const __half2*>(&b.z);
    __half2 b3 = *reinterpret_cast<const __half2*>(&b.w);
    __half2 acc = __hmul2(a0, b0);
    acc = __hfma2(a1, b1, acc);
    acc = __hfma2(a2, b2, acc);
    acc = __hfma2(a3, b3, acc);
    float2 f = __half22float2(acc);
    return f.x + f.y;
}

__device__ __forceinline__ unsigned ord_of_f(float f) {
    unsigned b = __float_as_uint(f);
    return b ^ (((unsigned)((int)b >> 31)) | 0x80000000u);
}
__device__ __forceinline__ float f_of_ord(unsigned u) {
    unsigned b = (u & 0x80000000u) ? (u ^ 0x80000000u) : ~u;
    return __uint_as_float(b);
}

// Reduce 8 values across 8 lanes (3 exchange stages); lane n gets total n.
__device__ __forceinline__ void tree8x8(float v[8], unsigned mask, int lane) {
    {   bool hi = (lane & 4) != 0;
        #pragma unroll
        for (int j = 0; j < 4; j++) {
            float mine = hi ? v[j] : v[j + 4];
            float kept = hi ? v[j + 4] : v[j];
            v[j] = kept + __shfl_xor_sync(mask, mine, 4);
        } }
    {   bool hi = (lane & 2) != 0;
        #pragma unroll
        for (int j = 0; j < 2; j++) {
            float mine = hi ? v[j] : v[j + 2];
            float kept = hi ? v[j + 2] : v[j];
            v[j] = kept + __shfl_xor_sync(mask, mine, 2);
        } }
    {   bool hi = (lane & 1) != 0;
        float mine = hi ? v[0] : v[1];
        float kept = hi ? v[1] : v[0];
        v[0] = kept + __shfl_xor_sync(mask, mine, 1);
    }
}

// ---- prep: transpose+normalize+fp16 xs/xe, softmax, trg compaction ----
__device__ __forceinline__ void transpose_block(const float* __restrict__ src,
                                                __half* __restrict__ dst,
                                                int blk, int t) {
    __shared__ float sm[FC][33];
    int pix0 = blk * 32;
    int b   = pix0 / HWp;
    int hw0 = pix0 - b * HWp;

    int px = t & 31, cb = (t >> 5) * 8;
    const float* sp = src + (size_t)b * FC * HWp + hw0 + px;
    #pragma unroll
    for (int j = 0; j < 8; j++)
        sm[cb + j][px] = sp[(size_t)(cb + j) * HWp];
    __syncthreads();

    int px2 = t >> 3, part = t & 7;
    float v[8];
    float ss = 0.f;
    #pragma unroll
    for (int j = 0; j < 8; j++) {
        v[j] = sm[part * 8 + j][px2];
        ss = fmaf(v[j], v[j], ss);
    }
    #pragma unroll
    for (int o = 4; o; o >>= 1) ss += __shfl_xor_sync(0xffffffffu, ss, o);
    float rn = 1.f / fmaxf(sqrtf(ss), EPSV);   // fp32 normalize, then round
    __half h[8];
    #pragma unroll
    for (int j = 0; j < 8; j++) h[j] = __float2half_rn(v[j] * rn);
    *reinterpret_cast<uint4*>(
        (char*)dst + (size_t)(pix0 + px2) * FBH + part * 16) =
        *reinterpret_cast<const uint4*>(h);
}

__global__ void __launch_bounds__(256)
k_prep(const float* __restrict__ xs, const float* __restrict__ xe,
       const float* __restrict__ logits, const float* __restrict__ mix) {
    int bx = blockIdx.x;
    int t = threadIdx.x;
    if (bx < NT) {
        transpose_block(xs, g_xs, bx, t);
    } else if (bx < 2 * NT) {
        transpose_block(xe, g_xe, bx - NT, t);
    } else if (bx < 2 * NT + NSOFT) {
        int sb = bx - 2 * NT;
        if (sb == 0 && t < 8) g_acc[t] = 0.0;
        if (sb == 0 && t == 8) g_done = 0;
        int pix = sb * 256 + t;
        int b  = pix / HWp;
        int hw = pix - b * HWp;
        const float* lb = logits + (size_t)b * NC * HWp + hw;
        float l[NC];
        float mx = -3.4e38f;
        #pragma unroll
        for (int c = 0; c < NC; c++) {
            l[c] = lb[(size_t)c * HWp];
            mx = fmaxf(mx, l[c]);
        }
        float s = 0.f;
        #pragma unroll
        for (int c = 0; c < NC; c++) { l[c] = expf(l[c] - mx); s += l[c]; }
        float inv = 1.f / s;
        #pragma unroll
        for (int c = 0; c < NC; c++) g_pp[(size_t)pix * NCP + c] = l[c] * inv;
        g_pp[(size_t)pix * NCP + NC] = 0.f;
    } else {
        // compaction: active target pixels -> worklist (interior / border)
        int cbk = bx - 2 * NT - NSOFT;
        int pix = cbk * 256 + t;
        bool a = (1.f - mix[pix]) > 0.5f;
        int hw = pix & (HWp - 1);
        int h = hw >> 7, w = hw & 127;
        bool inter = (h >= 3) && (h <= 124) && (w >= 3) && (w <= 124);
        unsigned mI = __ballot_sync(0xffffffffu, a && inter);
        unsigned mB = __ballot_sync(0xffffffffu, a && !inter);
        int lane = t & 31;
        int bI = 0, bB = 0;
        if (lane == 0) {
            if (mI) bI = atomicAdd(&g_nint, __popc(mI));
            if (mB) bB = atomicAdd(&g_nbrd, __popc(mB));
        }
        bI = __shfl_sync(0xffffffffu, bI, 0);
        bB = __shfl_sync(0xffffffffu, bB, 0);
        unsigned below = (1u << lane) - 1u;
        if (a && inter)  g_wl[bI + __popc(mI & below)] = pix;
        if (a && !inter) g_wl[NPIX - 1 - (bB + __popc(mB & below))] = pix;
    }
}

// ---- src path: pair-symmetric sims AND counts over 24 forward neighbors ----
__device__ __forceinline__ void src_path(const int* __restrict__ gt, int bx) {
    int b  = bx >> 9;
    int tt = bx & 511;                // 16x32 tiles of 8x4
    int h0 = (tt >> 5) << 3;
    int w0 = (tt & 31) << 2;
    int g    = threadIdx.x >> 3;      // 0..31 pixel in tile
    int lane = threadIdx.x & 7;
    unsigned gmask = 0xFFu << (threadIdx.x & 24);
    int h = h0 + (g >> 2), w = w0 + (g & 3);
    int pix = b * HWp + h * WW + w;

    bool interior = (h0 >= 8) && (h0 <= 112) && (w0 >= 4) && (w0 <= 120);

    int gc = gt[pix];
    float wp = (gc != 255) ? 1.f : 0.f;

    float sp = 0.f, sn = 0.f, cp = 0.f, nv = 0.f;

    // coalesced: 8 lanes x 16B = exactly one 128B row
    const char* Pl = (const char*)g_xs + (size_t)pix * FBH + lane * 16;
    uint4 f = *(const uint4*)Pl;
    const int* Pg = gt + pix;

    if (interior) {
        #pragma unroll
        for (int c = 0; c < 3; c++) {
            #pragma unroll
            for (int n = 0; n < 8; n++) {
                int k  = 25 + c * 8 + n;         // compile-time
                int dy = k / KK - 3;
                int dx = k - (k / KK) * KK - 3;
                int off = dy * WW + dx;
                uint4 nf = *(const uint4*)(Pl + (ptrdiff_t)off * FBH);
                float s = hdot8(f, nf);
                int gq = Pg[off];
                float wgt = wp + ((gq != 255) ? 1.f : 0.f);
                if (gq == gc) { sp = fmaf(wgt, s, sp); cp += wgt; }
                else          { sn = fmaf(wgt, s, sn); }
            }
        }
    } else {
        #pragma unroll 1
        for (int k = 25; k < K2; k++) {
            int dy = k / KK - 3;
            int dx = k - (k / KK) * KK - 3;
            int hn = h + dy, wn = w + dx;
            if ((unsigned)hn < (unsigned)HH && (unsigned)wn < (unsigned)WW) {
                int off = dy * WW + dx;
                uint4 nf = *(const uint4*)(Pl + (ptrdiff_t)off * FBH);
                float s = hdot8(f, nf);
                int gq = Pg[off];
                float wgt = wp + ((gq != 255) ? 1.f : 0.f);
                if (gq == gc) { sp = fmaf(wgt, s, sp); cp += wgt; }
                else          { sn = fmaf(wgt, s, sn); }
            }
        }
    }
    if (lane == 0) {
        sp += wp;        // center pair (k=24): sim = 1, pos
        nv  = wp;
    }

    #pragma unroll
    for (int o = 4; o; o >>= 1) {
        sp += __shfl_xor_sync(gmask, sp, o);
        sn += __shfl_xor_sync(gmask, sn, o);
        cp += __shfl_xor_sync(gmask, cp, o);
        nv += __shfl_xor_sync(gmask, nv, o);
    }
    __shared__ float sa[4];
    if (threadIdx.x < 4) sa[threadIdx.x] = 0.f;
    __syncthreads();
    if (lane == 0) {
        float cpFull = cp * 0.125f + wp;          // lanes identical -> /8 exact
        if (gc == 0) {                            // OOB neighbors count as class 0
            int y0 = max(h - 3, 0), y1 = min(h + 3, HH - 1);
            int x0 = max(w - 3, 0), x1 = min(w + 3, WW - 1);
            int nIn = (y1 - y0 + 1) * (x1 - x0 + 1);
            cpFull += wp * (float)(K2 - nIn);
        }
        atomicAdd(&sa[0], sp);
        atomicAdd(&sa[1], cpFull);
        atomicAdd(&sa[2], sn);
        atomicAdd(&sa[3], nv);
    }
    __syncthreads();
    if (threadIdx.x == 0) {
        atomicAdd(&g_acc[0], (double)sa[0]);
        atomicAdd(&g_acc[1], (double)sa[1]);
        atomicAdd(&g_acc[2], (double)sa[2]);
        atomicAdd(&g_acc[3], (double)sa[3]);
    }
}

// ---- trg interior: worklist entries, branch-free fast path everywhere ----
__device__ __forceinline__ void trg_int(int bx) {
    __shared__ float sm_s[K2][36];
    __shared__ unsigned long long sel[32][18];
    __shared__ float sred[3];

    int nInt = g_nint;
    int base = bx * 32;
    if (base >= nInt) return;       // idle block (uniform)

    int g    = threadIdx.x >> 3;
    int lane = threadIdx.x & 7;
    unsigned gmask = 0xFFu << (threadIdx.x & 24);
    int idx = base + g;
    bool act = idx < nInt;
    int pix = g_wl[act ? idx : base];

    if (act) {
        const char* Pl = (const char*)g_xe + (size_t)pix * FBH + lane * 16;
        uint4 f = *(const uint4*)Pl;
        #pragma unroll
        for (int c = 0; c < 6; c++) {
            float sv[8];
            #pragma unroll
            for (int n = 0; n < 8; n++) {
                int k  = c * 8 + n;
                int dy = k / KK - 3;
                int dx = k - (k / KK) * KK - 3;
                int off = dy * WW + dx;
                uint4 nf = *(const uint4*)(Pl + (ptrdiff_t)off * FBH);
                sv[n] = hdot8(f, nf);
            }
            tree8x8(sv, gmask, lane);
            sm_s[c * 8 + lane][g] = sv[0];
        }
        {   // straggler k = 48
            uint4 nf = *(const uint4*)(Pl + (ptrdiff_t)(3 * WW + 3) * FBH);
            float pd = hdot8(f, nf);
            #pragma unroll
            for (int o = 4; o; o >>= 1)
                pd += __shfl_xor_sync(gmask, pd, o);
            if (lane == 0) sm_s[48][g] = pd;
        }
    }
    if (threadIdx.x < 3) sred[threadIdx.x] = 0.f;
    __syncthreads();

    // phase 2a: selection (64 threads, 32 top + 32 bottom)
    if (threadIdx.x < 64) {
        int t = threadIdx.x;
        int q2 = t & 31;
        if (base + q2 < nInt) {
            if (t < 32) {
                unsigned long long key[NTOP];
                #pragma unroll
                for (int i = 0; i < NTOP; i++) key[i] = 0ull;
                #pragma unroll 1
                for (int k = 0; k < K2; k++) {
                    unsigned long long kk =
                        ((unsigned long long)ord_of_f(sm_s[k][q2]) << 8)
                        | (unsigned)(63 - k);
                    if (kk > key[NTOP - 1]) {
                        #pragma unroll
                        for (int i = 0; i < NTOP; i++)
                            if (kk > key[i]) {
                                unsigned long long x = key[i]; key[i] = kk; kk = x;
                            }
                    }
                }
                #pragma unroll
                for (int i = 0; i < NTOP; i++) sel[q2][i] = key[i];
            } else {
                unsigned long long key[NBOT];
                #pragma unroll
                for (int i = 0; i < NBOT; i++) key[i] = ~0ull;
                #pragma unroll 1
                for (int k = 0; k < K2; k++) {
                    unsigned long long kk =
                        ((unsigned long long)ord_of_f(sm_s[k][q2]) << 8)
                        | (unsigned)k;
                    if (kk < key[NBOT - 1]) {
                        #pragma unroll
                        for (int i = 0; i < NBOT; i++)
                            if (kk < key[i]) {
                                unsigned long long x = key[i]; key[i] = kk; kk = x;
                            }
                    }
                }
                #pragma unroll
                for (int i = 0; i < NBOT; i++) sel[q2][NTOP + i] = key[i];
            }
        }
    }
    __syncthreads();

    // phase 2b: 17 selected prob dots (interior: no bounds checks)
    float ssp = 0.f, ssn = 0.f, cnt = 0.f;
    if (act) {
        if (lane == 0) cnt = 1.f;
        const float4* A = reinterpret_cast<const float4*>(g_pp + (size_t)pix * NCP);
        float4 A0 = A[0], A1 = A[1], A2 = A[2], A3 = A[3], A4 = A[4];
        #pragma unroll 1
        for (int tid = lane; tid < NTOP + NBOT; tid += 8) {
            unsigned long long kk = sel[g][tid];
            bool isTop = tid < NTOP;
            int k = isTop ? (63 - (int)(kk & 63u)) : (int)(kk & 63u);
            float val = f_of_ord((unsigned)(kk >> 8));
            int dy = ((k * 9363) >> 16) - 3;
            int dx = k - (dy + 3) * KK - 3;
            const float4* Bv = reinterpret_cast<const float4*>(
                g_pp + (size_t)(pix + dy * WW + dx) * NCP);
            float cpv = dot4(A0, Bv[0]);
            cpv += dot4(A1, Bv[1]);
            cpv += dot4(A2, Bv[2]);
            cpv += dot4(A3, Bv[3]);
            cpv += dot4(A4, Bv[4]);
            if (isTop) ssp = fmaf(val, -cpv, ssp);
            else       ssn += (1.f - val) * (-(1.f - cpv));
        }
    }
    #pragma unroll
    for (int o = 16; o; o >>= 1) {
        ssp += __shfl_xor_sync(0xffffffffu, ssp, o);
        ssn += __shfl_xor_sync(0xffffffffu, ssn, o);
        cnt += __shfl_xor_sync(0xffffffffu, cnt, o);
    }
    if ((threadIdx.x & 31) == 0) {
        atomicAdd(&sred[0], ssp);
        atomicAdd(&sred[1], ssn);
        atomicAdd(&sred[2], cnt);
    }
    __syncthreads();
    if (threadIdx.x == 0) {
        atomicAdd(&g_acc[4], (double)sred[0]);
        atomicAdd(&g_acc[5], (double)sred[1]);
        atomicAdd(&g_acc[6], (double)sred[2]);
    }
}

// ---- trg border: worklist entries from back, bounds-checked path ----
__device__ __forceinline__ void trg_brd(int bx) {
    __shared__ float sm_s[K2][36];
    __shared__ unsigned long long sel[32][18];
    __shared__ float sred[3];

    int nBrd = g_nbrd;
    int base = bx * 32;
    if (base >= nBrd) return;

    int g    = threadIdx.x >> 3;
    int lane = threadIdx.x & 7;
    unsigned gmask = 0xFFu << (threadIdx.x & 24);
    int idx = base + g;
    bool act = idx < nBrd;
    int pix = g_wl[NPIX - 1 - (act ? idx : base)];
    int hw = pix & (HWp - 1);
    int h = hw >> 7, w = hw & 127;

    if (act) {
        const char* Pl = (const char*)g_xe + (size_t)pix * FBH + lane * 16;
        uint4 f = *(const uint4*)Pl;
        int k = 0;
        #pragma unroll 1
        for (int ky = 0; ky < KK; ky++) {
            int hn = h + ky - 3;
            bool rv = (unsigned)hn < (unsigned)HH;
            int hc = min(max(hn, 0), HH - 1);
            #pragma unroll
            for (int kx = 0; kx < KK; kx++, k++) {
                int wn = w + kx - 3;
                bool ok = rv && ((unsigned)wn < (unsigned)WW);
                int wc = min(max(wn, 0), WW - 1);
                int pn = (pix & ~(HWp - 1)) + hc * WW + wc;
                const char* Pn = (const char*)g_xe + (size_t)pn * FBH + lane * 16;
                uint4 nf = *(const uint4*)Pn;
                float pd = hdot8(f, nf);
                #pragma unroll
                for (int o = 4; o; o >>= 1)
                    pd += __shfl_xor_sync(gmask, pd, o);
                if (lane == 0) sm_s[k][g] = ok ? pd : 0.f;
            }
        }
    }
    if (threadIdx.x < 3) sred[threadIdx.x] = 0.f;
    __syncthreads();

    if (threadIdx.x < 64) {
        int t = threadIdx.x;
        int q2 = t & 31;
        if (base + q2 < nBrd) {
            if (t < 32) {
                unsigned long long key[NTOP];
                #pragma unroll
                for (int i = 0; i < NTOP; i++) key[i] = 0ull;
                #pragma unroll 1
                for (int k = 0; k < K2; k++) {
                    unsigned long long kk =
                        ((unsigned long long)ord_of_f(sm_s[k][q2]) << 8)
                        | (unsigned)(63 - k);
                    if (kk > key[NTOP - 1]) {
                        #pragma unroll
                        for (int i = 0; i < NTOP; i++)
                            if (kk > key[i]) {
                                unsigned long long x = key[i]; key[i] = kk; kk = x;
                            }
                    }
                }
                #pragma unroll
                for (int i = 0; i < NTOP; i++) sel[q2][i] = key[i];
            } else {
                unsigned long long key[NBOT];
                #pragma unroll
                for (int i = 0; i < NBOT; i++) key[i] = ~0ull;
                #pragma unroll 1
                for (int k = 0; k < K2; k++) {
                    unsigned long long kk =
                        ((unsigned long long)ord_of_f(sm_s[k][q2]) << 8)
                        | (unsigned)k;
                    if (kk < key[NBOT - 1]) {
                        #pragma unroll
                        for (int i = 0; i < NBOT; i++)
                            if (kk < key[i]) {
                                unsigned long long x = key[i]; key[i] = kk; kk = x;
                            }
                    }
                }
                #pragma unroll
                for (int i = 0; i < NBOT; i++) sel[q2][NTOP + i] = key[i];
            }
        }
    }
    __syncthreads();

    float ssp = 0.f, ssn = 0.f, cnt = 0.f;
    if (act) {
        if (lane == 0) cnt = 1.f;
        const float4* A = reinterpret_cast<const float4*>(g_pp + (size_t)pix * NCP);
        float4 A0 = A[0], A1 = A[1], A2 = A[2], A3 = A[3], A4 = A[4];
        #pragma unroll 1
        for (int tid = lane; tid < NTOP + NBOT; tid += 8) {
            unsigned long long kk = sel[g][tid];
            bool isTop = tid < NTOP;
            int k = isTop ? (63 - (int)(kk & 63u)) : (int)(kk & 63u);
            float val = f_of_ord((unsigned)(kk >> 8));
            int dy = ((k * 9363) >> 16) - 3;
            int dx = k - (dy + 3) * KK - 3;
            int hn = h + dy, wn = w + dx;
            float cpv = 1.f / 19.f;
            if ((unsigned)hn < (unsigned)HH && (unsigned)wn < (unsigned)WW) {
                const float4* Bv = reinterpret_cast<const float4*>(
                    g_pp + (size_t)(pix + dy * WW + dx) * NCP);
                float d2 = dot4(A0, Bv[0]);
                d2 += dot4(A1, Bv[1]);
                d2 += dot4(A2, Bv[2]);
                d2 += dot4(A3, Bv[3]);
                d2 += dot4(A4, Bv[4]);
                cpv = d2;
            }
            if (isTop) ssp = fmaf(val, -cpv, ssp);
            else       ssn += (1.f - val) * (-(1.f - cpv));
        }
    }
    #pragma unroll
    for (int o = 16; o; o >>= 1) {
        ssp += __shfl_xor_sync(0xffffffffu, ssp, o);
        ssn += __shfl_xor_sync(0xffffffffu, ssn, o);
        cnt += __shfl_xor_sync(0xffffffffu, cnt, o);
    }
    if ((threadIdx.x & 31) == 0) {
        atomicAdd(&sred[0], ssp);
        atomicAdd(&sred[1], ssn);
        atomicAdd(&sred[2], cnt);
    }
    __syncthreads();
    if (threadIdx.x == 0) {
        atomicAdd(&g_acc[4], (double)sred[0]);
        atomicAdd(&g_acc[5], (double)sred[1]);
        atomicAdd(&g_acc[6], (double)sred[2]);
    }
}

// ---- merged main: border + interleaved src/trg-int + finalize/reset ----
__global__ void __launch_bounds__(256, 5)
k_main(const int* __restrict__ gt, float* __restrict__ out) {
    int bx = blockIdx.x;
    if (bx < TRGB_BLOCKS) {
        trg_brd(bx);
    } else {
        int r = bx - TRGB_BLOCKS;
        if (r < 2 * TRGI_BLOCKS) {
            if (r & 1) trg_int(r >> 1);
            else       src_path(gt, r >> 1);
        } else {
            src_path(gt, TRGI_BLOCKS + (r - 2 * TRGI_BLOCKS));
        }
    }

    __shared__ bool isLast;
    if (threadIdx.x == 0) {
        __threadfence();
        int prev = atomicAdd(&g_done, 1);
        isLast = (prev == MAIN_BLOCKS - 1);
    }
    __syncthreads();
    if (isLast && threadIdx.x == 0) {
        double cntP = g_acc[1];
        double cntN = 49.0 * g_acc[3] - cntP;
        double src_pos = g_acc[0] / fmax(cntP, 1.0);
        double src_neg = g_acc[2] / fmax(cntN, 1.0);
        double sim_pos = g_acc[4] / fmax((double)NTOP * g_acc[6], 1.0);
        double sim_neg = g_acc[5] / fmax((double)NBOT * g_acc[6], 1.0);
        out[0] = (float)(-src_pos);
        out[1] = (float)( src_neg);
        out[2] = (float)( sim_pos);
        out[3] = (float)( sim_neg);
        g_nint = 0;          // reset for next graph replay
        g_nbrd = 0;
    }
}

extern "C" void kernel_launch(void* const* d_in, const int* in_sizes, int n_in,
                              void* d_out, int out_size) {
    (void)in_sizes; (void)n_in; (void)out_size;
    const float* logits = (const float*)d_in[0];
    const int*   gt     = (const int*)d_in[1];
    const float* xe     = (const float*)d_in[2];
    const float* xs     = (const float*)d_in[3];
    const float* mix    = (const float*)d_in[4];
    float* out = (float*)d_out;

    k_prep<<<2 * NT + NSOFT + NCOMP, 256>>>(xs, xe, logits, mix);
    k_main<<<MAIN_BLOCKS, 256>>>(gt, out);
}